// round 7
// baseline (speedup 1.0000x reference)
#include <cuda_runtime.h>
#include <cuda_bf16.h>
#include <cstdint>

// Problem constants
#define Hn 1024
#define Bn 128
#define Tn 400
#define Sn 64
#define Cn 8
#define NOUTn 3
#define NCLSn 3
#define BOTn 2
#define CLSOUTn 8
#define NEXC 819              // int(1024 * 0.8)

#define NCTA 128
#define NTHR 512
#define JPC 8                 // j columns per CTA in phase B
#define KSL 128               // k-slice per CTA in phase A
#define JSL 64                // j-slice per CTA in phase A
#define NKC 8                 // number of k slices

#define ALPHA_N 0.2f
#define DT_SEC 0.02f
#define NZ_SCALE 0.25f        // NOISE_STD / ALPHA_N
#define AX_SLOW ((float)(20.0 / 1500.0))
#define AX_FAST ((float)(20.0 / 200.0))

#define NR (NOUTn + NCLSn * CLSOUTn)   // 27 fused readout rows
#define PR_ROWS 32

// smem layout (floats): w_sm[8192] | hp_sm[16384] | comb[27*1024]
#define SM_W 0
#define SM_HP 8192
#define SM_COMB (8192 + 16384)
#define SMEM_BYTES ((8192 + 16384 + NR * Hn) * 4)

// ---------------- device scratch ----------------
__device__ float g_drive[(size_t)Tn * Hn * Bn];        // [t][h][b], noise folded
__device__ float g_hp[2][Hn * Bn];                     // h_post [k][b], double buffered
__device__ float g_part[2][(size_t)NKC * Hn * Bn];     // [par][kc][j][b]
__device__ float g_comb[NR * Hn];
__device__ float g_combb[NR];
__device__ unsigned g_count;                           // phase-transition counter
__device__ unsigned g_kcnt[NKC * 32];                  // partial-ready counts (padded)
__device__ unsigned g_hcnt[NKC * 32];                  // h_post-ready counts (padded)

// ---------------- sync helpers (morally-strong release/acquire) ----------------
__device__ __forceinline__ void red_rel(unsigned* p) {
    asm volatile("red.release.gpu.global.add.u32 [%0], 1;" :: "l"(p) : "memory");
}
__device__ __forceinline__ unsigned ld_acq(const unsigned* p) {
    unsigned v;
    asm volatile("ld.acquire.gpu.global.u32 %0, [%1];" : "=r"(v) : "l"(p) : "memory");
    return v;
}
__device__ __forceinline__ void announce(unsigned* p) {
    __threadfence();
    __syncthreads();
    if (threadIdx.x == 0) red_rel(p);
}

// ---------------- packed f32x2 helpers ----------------
__device__ __forceinline__ unsigned long long fma2(unsigned long long a,
                                                   unsigned long long b,
                                                   unsigned long long c) {
    unsigned long long d;
    asm("fma.rn.f32x2 %0, %1, %2, %3;" : "=l"(d) : "l"(a), "l"(b), "l"(c));
    return d;
}
__device__ __forceinline__ unsigned long long pack2(float v) {
    unsigned long long d;
    unsigned r = __float_as_uint(v);
    asm("mov.b64 %0, {%1, %2};" : "=l"(d) : "r"(r), "r"(r));
    return d;
}
__device__ __forceinline__ void unpack2(unsigned long long p, float& lo, float& hi) {
    unsigned a, b;
    asm("mov.b64 {%0, %1}, %2;" : "=r"(a), "=r"(b) : "l"(p));
    lo = __uint_as_float(a);
    hi = __uint_as_float(b);
}
__device__ __forceinline__ void cp_async16(uint32_t saddr, const void* gaddr) {
    asm volatile("cp.async.cg.shared.global [%0], [%1], 16;" :: "r"(saddr), "l"(gaddr));
}
__device__ __forceinline__ void cp_commit() {
    asm volatile("cp.async.commit_group;");
}
template <int N>
__device__ __forceinline__ void cp_wait() {
    asm volatile("cp.async.wait_group %0;" :: "n"(N));
}

__device__ __forceinline__ void gbar(unsigned target) {
    __threadfence();
    __syncthreads();
    if (threadIdx.x == 0) {
        red_rel(&g_count);
        while (ld_acq(&g_count) < target) { }
    }
    __syncthreads();
}

// ---------------- reset (graph-replay determinism) ----------------
__global__ void reset_kernel() {
    int i = threadIdx.x;
    if (i == 0) g_count = 0;
    if (i < NKC * 32) { g_kcnt[i] = 0; g_hcnt[i] = 0; }
}

// ---------------- the single persistent kernel ----------------
__global__ void __launch_bounds__(NTHR, 1) mega_kernel(
        const float* __restrict__ stim,
        const float* __restrict__ ctx,
        const float* __restrict__ w_rec,
        const float* __restrict__ b_rec,
        const float* __restrict__ w_in,
        const float* __restrict__ w_ctx,
        const float* __restrict__ w_out,
        const float* __restrict__ b_out,
        const float* __restrict__ c1_w,
        const float* __restrict__ c1_b,
        const float* __restrict__ c2_w,
        const float* __restrict__ c2_b,
        const float* __restrict__ noise,
        float* __restrict__ out0,
        float* __restrict__ acts,
        float* __restrict__ pout) {
    extern __shared__ float sm[];
    float* w_sm  = sm + SM_W;     // [128][64]
    float* hp_sm = sm + SM_HP;    // [128][128]

    const int c   = blockIdx.x;
    const int tid = threadIdx.x;
    // phase A roles: 512 threads = 32 b-quads x 16 j-quads
    const int kc = c >> 4, jc = c & 15;
    const int q  = tid & 31;              // b-quad: b = 4q..4q+3
    const int w  = tid >> 5;              // j-quad: j_local = 4w..4w+3 (0..15)
    const int kc32 = kc * 32;
    // phase B roles: 512 threads = 128 b x 4 column-pairs
    const int b  = tid & 127;
    const int g  = tid >> 7;              // 0..3
    const int j0 = c * JPC;
    const int jg = j0 + 2 * g;            // this thread's 2 columns (even start)

    // ---- P0a: classifier fusion ----
    {
        int idx = c * NTHR + tid;
        if (idx < NOUTn * Hn) g_comb[idx] = w_out[idx];
        if (idx < NCLSn * CLSOUTn * Hn) {
            int r = idx / Hn, h = idx % Hn;
            int j = r / CLSOUTn, o = r % CLSOUTn;
            float acc = 0.f;
            #pragma unroll
            for (int k = 0; k < BOTn; k++)
                acc += c2_w[(j * CLSOUTn + o) * BOTn + k] * c1_w[(j * BOTn + k) * Hn + h];
            g_comb[(NOUTn + r) * Hn + h] = acc;
        }
        if (idx < NOUTn) g_combb[idx] = b_out[idx];
        if (idx >= NOUTn && idx < NR) {
            int r = idx - NOUTn;
            int j = r / CLSOUTn, o = r % CLSOUTn;
            float acc = c2_b[j * CLSOUTn + o];
            #pragma unroll
            for (int k = 0; k < BOTn; k++)
                acc += c2_w[(j * CLSOUTn + o) * BOTn + k] * c1_b[j * BOTn + k];
            g_combb[idx] = acc;
        }
    }

    // ---- P0b: W slice into smem ----
    for (int idx = tid; idx < KSL * JSL; idx += NTHR) {
        int kl = idx >> 6, jl = idx & 63;
        int k = kc * KSL + kl, j = jc * JSL + jl;
        float ww = fmaxf(w_rec[(size_t)k * Hn + j], 0.f);
        if (k == j) ww = 0.f;
        w_sm[idx] = (k < NEXC) ? ww : -ww;
    }
    float br[2];
    br[0] = b_rec[jg];
    br[1] = b_rec[jg + 1];

    // ---- P0c: initial h_post(0) = 0, announce ----
    g_hp[0][jg * Bn + b] = 0.f;
    g_hp[0][(jg + 1) * Bn + b] = 0.f;
    announce(&g_hcnt[kc32]);

    // ---- P1: drive precompute, grid-stride over 800 (t, 512h) units ----
    {
        const int gg = tid >> 7;          // 0..3: which 128-h block
        const int bb = tid & 127;
        for (int u = c; u < Tn * 2; u += NCTA) {
            const int t = u % Tn;
            const int h0 = (u / Tn) * 512 + gg * 128;

            float sin_r[Sn], cin_r[Cn];
            const float4* sp = (const float4*)(stim + ((size_t)bb * Tn + t) * Sn);
            #pragma unroll
            for (int p = 0; p < Sn / 4; p++) {
                float4 v = sp[p];
                sin_r[4*p] = v.x; sin_r[4*p+1] = v.y; sin_r[4*p+2] = v.z; sin_r[4*p+3] = v.w;
            }
            const float4* cpp = (const float4*)(ctx + ((size_t)bb * Tn + t) * Cn);
            #pragma unroll
            for (int p = 0; p < Cn / 4; p++) {
                float4 v = cpp[p];
                cin_r[4*p] = v.x; cin_r[4*p+1] = v.y; cin_r[4*p+2] = v.z; cin_r[4*p+3] = v.w;
            }
            const float4* nzp = (const float4*)(noise + ((size_t)t * Bn + bb) * Hn);

            for (int hh = 0; hh < 128; hh += 4) {
                const int h = h0 + hh;
                float acc0 = 0.f, acc1 = 0.f, acc2 = 0.f, acc3 = 0.f;
                #pragma unroll
                for (int s4 = 0; s4 < Sn / 4; s4++) {
                    float4 w0 = *(const float4*)(w_in + (size_t)(h + 0) * Sn + s4 * 4);
                    float4 w1 = *(const float4*)(w_in + (size_t)(h + 1) * Sn + s4 * 4);
                    float4 w2 = *(const float4*)(w_in + (size_t)(h + 2) * Sn + s4 * 4);
                    float4 w3 = *(const float4*)(w_in + (size_t)(h + 3) * Sn + s4 * 4);
                    float i0 = sin_r[4*s4], i1 = sin_r[4*s4+1];
                    float i2 = sin_r[4*s4+2], i3 = sin_r[4*s4+3];
                    acc0 = fmaf(i0, w0.x, acc0); acc0 = fmaf(i1, w0.y, acc0);
                    acc0 = fmaf(i2, w0.z, acc0); acc0 = fmaf(i3, w0.w, acc0);
                    acc1 = fmaf(i0, w1.x, acc1); acc1 = fmaf(i1, w1.y, acc1);
                    acc1 = fmaf(i2, w1.z, acc1); acc1 = fmaf(i3, w1.w, acc1);
                    acc2 = fmaf(i0, w2.x, acc2); acc2 = fmaf(i1, w2.y, acc2);
                    acc2 = fmaf(i2, w2.z, acc2); acc2 = fmaf(i3, w2.w, acc2);
                    acc3 = fmaf(i0, w3.x, acc3); acc3 = fmaf(i1, w3.y, acc3);
                    acc3 = fmaf(i2, w3.z, acc3); acc3 = fmaf(i3, w3.w, acc3);
                }
                #pragma unroll
                for (int c4 = 0; c4 < Cn / 4; c4++) {
                    float4 w0 = *(const float4*)(w_ctx + (size_t)(h + 0) * Cn + c4 * 4);
                    float4 w1 = *(const float4*)(w_ctx + (size_t)(h + 1) * Cn + c4 * 4);
                    float4 w2 = *(const float4*)(w_ctx + (size_t)(h + 2) * Cn + c4 * 4);
                    float4 w3 = *(const float4*)(w_ctx + (size_t)(h + 3) * Cn + c4 * 4);
                    float i0 = cin_r[4*c4], i1 = cin_r[4*c4+1];
                    float i2 = cin_r[4*c4+2], i3 = cin_r[4*c4+3];
                    acc0 = fmaf(i0, w0.x, acc0); acc0 = fmaf(i1, w0.y, acc0);
                    acc0 = fmaf(i2, w0.z, acc0); acc0 = fmaf(i3, w0.w, acc0);
                    acc1 = fmaf(i0, w1.x, acc1); acc1 = fmaf(i1, w1.y, acc1);
                    acc1 = fmaf(i2, w1.z, acc1); acc1 = fmaf(i3, w1.w, acc1);
                    acc2 = fmaf(i0, w2.x, acc2); acc2 = fmaf(i1, w2.y, acc2);
                    acc2 = fmaf(i2, w2.z, acc2); acc2 = fmaf(i3, w2.w, acc2);
                    acc3 = fmaf(i0, w3.x, acc3); acc3 = fmaf(i1, w3.y, acc3);
                    acc3 = fmaf(i2, w3.z, acc3); acc3 = fmaf(i3, w3.w, acc3);
                }
                float4 nz = nzp[h >> 2];
                float* gd = g_drive + ((size_t)t * Hn + h) * Bn + bb;
                gd[0]      = fmaf(NZ_SCALE, nz.x, acc0);
                gd[Bn]     = fmaf(NZ_SCALE, nz.y, acc1);
                gd[2 * Bn] = fmaf(NZ_SCALE, nz.z, acc2);
                gd[3 * Bn] = fmaf(NZ_SCALE, nz.w, acc3);
            }
        }
    }

    gbar(NCTA);   // drive complete

    // ---- P2: scan ----
    float h[2], sx[2], su[2];
    #pragma unroll
    for (int jj = 0; jj < 2; jj++) {
        h[jj] = 0.f;
        sx[jj] = 1.f;
        su[jj] = (jj & 1) ? 0.15f : 0.45f;   // jg even
    }

    const uint32_t hp_sm_addr = (uint32_t)__cvta_generic_to_shared(hp_sm);

    for (int step = 0; step < Tn; step++) {
        const unsigned stp1 = 16u * (unsigned)(step + 1);
        const int par = step & 1;

        // drive prefetch (overlaps the flag wait)
        const float* gd = g_drive + ((size_t)step * Hn + jg) * Bn + b;
        float d0 = __ldcg(gd), d1 = __ldcg(gd + Bn);

        // ---- wait: h_post rows for my k-slice ready (acquire, thread 0) ----
        if (tid == 0) {
            while (ld_acq(&g_hcnt[kc32]) < stp1) { }
        }
        __syncthreads();

        // ---- phase A: stage h_post k-slice, 4 x 16KB pipelined chunks ----
        {
            const float* src0 = g_hp[par] + (size_t)(kc * KSL) * Bn;
            #pragma unroll
            for (int ch = 0; ch < 4; ch++) {
                int s0i = ch * 1024 + tid;
                cp_async16(hp_sm_addr + s0i * 16, src0 + s0i * 4);
                int s1i = s0i + 512;
                cp_async16(hp_sm_addr + s1i * 16, src0 + s1i * 4);
                cp_commit();
            }
        }

        unsigned long long acc[4][2];
        #pragma unroll
        for (int bi = 0; bi < 4; bi++) {
            acc[bi][0] = 0ull;
            acc[bi][1] = 0ull;
        }

        const float* hprow = hp_sm + 4 * q;
        const ulonglong2* wrow = (const ulonglong2*)(w_sm + 4 * w);

        #define KBODY(kl_) {                                                  \
            float4 hp = *(const float4*)(hprow + (kl_) * Bn);                  \
            ulonglong2 wv = wrow[(kl_) * (JSL / 4)];                           \
            unsigned long long p0 = pack2(hp.x), p1 = pack2(hp.y);             \
            unsigned long long p2 = pack2(hp.z), p3 = pack2(hp.w);             \
            acc[0][0] = fma2(p0, wv.x, acc[0][0]);                             \
            acc[0][1] = fma2(p0, wv.y, acc[0][1]);                             \
            acc[1][0] = fma2(p1, wv.x, acc[1][0]);                             \
            acc[1][1] = fma2(p1, wv.y, acc[1][1]);                             \
            acc[2][0] = fma2(p2, wv.x, acc[2][0]);                             \
            acc[2][1] = fma2(p2, wv.y, acc[2][1]);                             \
            acc[3][0] = fma2(p3, wv.x, acc[3][0]);                             \
            acc[3][1] = fma2(p3, wv.y, acc[3][1]); }

        cp_wait<3>();
        __syncthreads();
        #pragma unroll 8
        for (int kl = 0; kl < 32; kl++) KBODY(kl)

        cp_wait<2>();
        __syncthreads();
        #pragma unroll 8
        for (int kl = 32; kl < 64; kl++) KBODY(kl)

        cp_wait<1>();
        __syncthreads();
        #pragma unroll 8
        for (int kl = 64; kl < 96; kl++) KBODY(kl)

        cp_wait<0>();
        __syncthreads();
        #pragma unroll 8
        for (int kl = 96; kl < 128; kl++) KBODY(kl)
        #undef KBODY

        // write partials [kc][j][b]: thread covers j = jc*64 + 4w + {0,1,2,3}, b = 4q..4q+3
        {
            float* gpart = g_part[par];
            int jbase = jc * JSL + 4 * w;
            #pragma unroll
            for (int jp = 0; jp < 2; jp++) {
                float l0, h0v, l1, h1v, l2, h2v, l3, h3v;
                unpack2(acc[0][jp], l0, h0v);
                unpack2(acc[1][jp], l1, h1v);
                unpack2(acc[2][jp], l2, h2v);
                unpack2(acc[3][jp], l3, h3v);
                int j = jbase + 2 * jp;
                *(float4*)(gpart + ((size_t)kc * Hn + j) * Bn + 4 * q) =
                    make_float4(l0, l1, l2, l3);
                *(float4*)(gpart + ((size_t)kc * Hn + j + 1) * Bn + 4 * q) =
                    make_float4(h0v, h1v, h2v, h3v);
            }
        }

        announce(&g_kcnt[kc32]);

        // ---- phase B: wait all 8 partial groups (acquire, thread 0) ----
        if (tid == 0) {
            for (;;) {
                unsigned ok = 1;
                #pragma unroll
                for (int k2 = 0; k2 < NKC; k2++)
                    ok &= (ld_acq(&g_kcnt[k2 * 32]) >= stp1) ? 1u : 0u;
                if (ok) break;
            }
        }
        __syncthreads();

        float s0 = 0.f, s1 = 0.f;
        {
            const float* gpart = g_part[par];
            #pragma unroll
            for (int k2 = 0; k2 < NKC; k2++) {
                const float* pp = gpart + ((size_t)k2 * Hn + jg) * Bn + b;
                s0 += __ldcg(pp);
                s1 += __ldcg(pp + Bn);
            }
        }
        float ss[2] = {s0, s1};
        float dd[2] = {d0, d1};
        float hn[2];
        #pragma unroll
        for (int jj = 0; jj < 2; jj++) {
            float val = h[jj] * (1.f - ALPHA_N)
                      + ALPHA_N * (dd[jj] + ss[jj] + br[jj]);
            hn[jj] = fmaxf(val, 0.f);
            h[jj] = hn[jj];
        }
        *(float2*)(acts + ((size_t)b * Tn + step) * Hn + jg) =
            make_float2(hn[0], hn[1]);

        // STP + h_post(step+1) into the other buffer, announce
        float* hpn = g_hp[par ^ 1];
        #pragma unroll
        for (int jj = 0; jj < 2; jj++) {
            const float axv = (jj & 1) ? AX_FAST : AX_SLOW;
            const float Uv  = (jj & 1) ? 0.15f : 0.45f;
            float hh = h[jj];
            float sxo = sx[jj], suo = su[jj];
            float sxn = sxo + axv * (1.f - sxo) - DT_SEC * suo * sxo * hh;
            float sun = suo + axv * (Uv - suo) + DT_SEC * Uv * (1.f - suo) * hh;
            sxn = fminf(fmaxf(sxn, 0.f), 1.f);
            sun = fminf(fmaxf(sun, 0.f), 1.f);
            sx[jj] = sxn; su[jj] = sun;
            hpn[(jg + jj) * Bn + b] = sun * sxn * hh;
        }
        announce(&g_hcnt[kc32]);
    }

    gbar(2 * NCTA);   // scan complete

    // ---- P3: post (fused readout), 16 warps x 2 rows ----
    {
        float* s_comb = sm + SM_COMB;
        for (int i = tid; i < NR * Hn; i += NTHR) s_comb[i] = g_comb[i];
        __syncthreads();

        const int wid = tid >> 5, lane = tid & 31;
        const float4* comb4 = (const float4*)s_comb;

        for (int u = c; u < (Bn * Tn) / PR_ROWS; u += NCTA) {
            #pragma unroll 1
            for (int rr = 0; rr < 2; rr++) {
                const int bt = u * PR_ROWS + wid * 2 + rr;
                const float4* a4 = (const float4*)(acts + (size_t)bt * Hn);

                float acc[NR];
                #pragma unroll
                for (int r = 0; r < NR; r++) acc[r] = 0.f;

                #pragma unroll
                for (int it = 0; it < Hn / 128; it++) {
                    float4 a = a4[it * 32 + lane];
                    #pragma unroll
                    for (int r = 0; r < NR; r++) {
                        float4 ww = comb4[r * 256 + it * 32 + lane];
                        float s = a.x * ww.x + a.y * ww.y;
                        s = fmaf(a.z, ww.z, s);
                        s = fmaf(a.w, ww.w, s);
                        acc[r] += s;
                    }
                }
                #pragma unroll
                for (int r = 0; r < NR; r++) {
                    #pragma unroll
                    for (int off = 16; off > 0; off >>= 1)
                        acc[r] += __shfl_down_sync(0xffffffffu, acc[r], off);
                }
                if (lane == 0) {
                    #pragma unroll
                    for (int r = 0; r < NOUTn; r++)
                        out0[(size_t)bt * NOUTn + r] = acc[r] + g_combb[r];
                    #pragma unroll
                    for (int r = NOUTn; r < NR; r++)
                        pout[(size_t)bt * (NCLSn * CLSOUTn) + (r - NOUTn)]
                            = acc[r] + g_combb[r];
                }
            }
        }
    }
}

// ---------------- launch ----------------
extern "C" void kernel_launch(void* const* d_in, const int* in_sizes, int n_in,
                              void* d_out, int out_size) {
    const float* stim  = (const float*)d_in[0];
    const float* ctx   = (const float*)d_in[1];
    const float* w_rec = (const float*)d_in[2];
    const float* b_rec = (const float*)d_in[3];
    const float* w_in  = (const float*)d_in[4];
    const float* w_ctx = (const float*)d_in[5];
    const float* w_out = (const float*)d_in[6];
    const float* b_out = (const float*)d_in[7];
    const float* c1_w  = (const float*)d_in[8];
    const float* c1_b  = (const float*)d_in[9];
    const float* c2_w  = (const float*)d_in[10];
    const float* c2_b  = (const float*)d_in[11];
    const float* noise = (const float*)d_in[12];

    float* out0 = (float*)d_out;                         // [B, T, 3]
    float* acts = out0 + (size_t)Bn * Tn * NOUTn;        // [B, T, H]
    float* pout = acts + (size_t)Bn * Tn * Hn;           // [B, T, 3, 8]

    static bool attr_set = false;
    if (!attr_set) {
        cudaFuncSetAttribute(mega_kernel,
                             cudaFuncAttributeMaxDynamicSharedMemorySize,
                             SMEM_BYTES);
        attr_set = true;
    }

    reset_kernel<<<1, 256>>>();
    mega_kernel<<<NCTA, NTHR, SMEM_BYTES>>>(
        stim, ctx, w_rec, b_rec, w_in, w_ctx, w_out, b_out,
        c1_w, c1_b, c2_w, c2_b, noise, out0, acts, pout);
}

// round 8
// speedup vs baseline: 1.4559x; 1.4559x over previous
#include <cuda_runtime.h>
#include <cuda_bf16.h>
#include <cstdint>

// Problem constants
#define Hn 1024
#define Bn 128
#define Tn 400
#define Sn 64
#define Cn 8
#define NOUTn 3
#define NCLSn 3
#define BOTn 2
#define CLSOUTn 8
#define NEXC 819              // int(1024 * 0.8)

#define NCTA 128
#define NTHR 256
#define JPC 8                 // j columns per CTA in phase B
#define KSL 128               // k-slice per CTA in phase A
#define JSL 64                // j-slice per CTA in phase A
#define NKC 8                 // number of k slices

#define ALPHA_N 0.2f
#define DT_SEC 0.02f
#define NZ_SCALE 0.25f        // NOISE_STD / ALPHA_N
#define AX_SLOW ((float)(20.0 / 1500.0))
#define AX_FAST ((float)(20.0 / 200.0))

#define NR (NOUTn + NCLSn * CLSOUTn)   // 27 fused readout rows
#define PR_ROWS 32

// smem word offsets
#define W_PITCH 72            // 64 j + 8 pad (words) -> conflict-free
#define HP_PITCH 136          // 128 b + 8 pad (words) -> conflict-free
#define SM_WHI 0              // 64 * 72 = 4608 words
#define SM_WLO 4608
#define SM_HPHI 9216          // 64 * 136 = 8704 words
#define SM_HPLO 17920
#define SM_COMB 0             // P3 reuses the W/hp space
#define SMEM_WORDS 27648      // max(26624 scan, 27648 comb)
#define SMEM_BYTES (SMEM_WORDS * 4)

// ---------------- device scratch ----------------
__device__ float g_drive[(size_t)Tn * Hn * Bn];        // [t][h][b], noise folded
__device__ unsigned g_hph[2][(Hn / 2) * Bn];           // h_post hi pairs [k/2][b]
__device__ unsigned g_hpl[2][(Hn / 2) * Bn];           // h_post lo pairs [k/2][b]
__device__ float g_part[2][(size_t)NKC * Hn * Bn];     // [par][kc][j][b]
__device__ float g_comb[NR * Hn];
__device__ float g_combb[NR];
__device__ unsigned g_count;                           // phase-transition counter
__device__ unsigned g_kcnt[NKC * 32];                  // partial-ready counts (padded)
__device__ unsigned g_hcnt[NKC * 32];                  // h_post-ready counts (padded)

// ---------------- sync helpers (morally-strong release/acquire) ----------------
__device__ __forceinline__ void red_rel(unsigned* p) {
    asm volatile("red.release.gpu.global.add.u32 [%0], 1;" :: "l"(p) : "memory");
}
__device__ __forceinline__ unsigned ld_acq(const unsigned* p) {
    unsigned v;
    asm volatile("ld.acquire.gpu.global.u32 %0, [%1];" : "=r"(v) : "l"(p) : "memory");
    return v;
}
__device__ __forceinline__ void announce(unsigned* p) {
    __threadfence();
    __syncthreads();
    if (threadIdx.x == 0) red_rel(p);
}

__device__ __forceinline__ void cp_async16(uint32_t saddr, const void* gaddr) {
    asm volatile("cp.async.cg.shared.global [%0], [%1], 16;" :: "r"(saddr), "l"(gaddr));
}
__device__ __forceinline__ void cp_commit() {
    asm volatile("cp.async.commit_group;");
}
template <int N>
__device__ __forceinline__ void cp_wait() {
    asm volatile("cp.async.wait_group %0;" :: "n"(N));
}

__device__ __forceinline__ void gbar(unsigned target) {
    __threadfence();
    __syncthreads();
    if (threadIdx.x == 0) {
        red_rel(&g_count);
        while (ld_acq(&g_count) < target) { }
    }
    __syncthreads();
}

// bf16 split helpers
__device__ __forceinline__ unsigned pack_pair_hi(float e, float o,
                                                 float& re, float& ro) {
    __nv_bfloat16 he = __float2bfloat16(e);
    __nv_bfloat16 ho = __float2bfloat16(o);
    re = e - __bfloat162float(he);
    ro = o - __bfloat162float(ho);
    return ((unsigned)__bfloat16_as_ushort(ho) << 16) |
           (unsigned)__bfloat16_as_ushort(he);
}
__device__ __forceinline__ unsigned pack_pair(float e, float o) {
    __nv_bfloat16 he = __float2bfloat16(e);
    __nv_bfloat16 ho = __float2bfloat16(o);
    return ((unsigned)__bfloat16_as_ushort(ho) << 16) |
           (unsigned)__bfloat16_as_ushort(he);
}

#define MMA16816(cr, a0_, a1_, a2_, a3_, b0_, b1_)                          \
    asm volatile("mma.sync.aligned.m16n8k16.row.col.f32.bf16.bf16.f32 "     \
        "{%0,%1,%2,%3}, {%4,%5,%6,%7}, {%8,%9}, {%0,%1,%2,%3};"             \
        : "+f"((cr)[0]), "+f"((cr)[1]), "+f"((cr)[2]), "+f"((cr)[3])        \
        : "r"(a0_), "r"(a1_), "r"(a2_), "r"(a3_), "r"(b0_), "r"(b1_))

// ---------------- reset (graph-replay determinism) ----------------
__global__ void reset_kernel() {
    int i = threadIdx.x;
    if (i == 0) g_count = 0;
    if (i < NKC * 32) { g_kcnt[i] = 0; g_hcnt[i] = 0; }
}

// ---------------- the single persistent kernel ----------------
__global__ void __launch_bounds__(NTHR, 1) mega_kernel(
        const float* __restrict__ stim,
        const float* __restrict__ ctx,
        const float* __restrict__ w_rec,
        const float* __restrict__ b_rec,
        const float* __restrict__ w_in,
        const float* __restrict__ w_ctx,
        const float* __restrict__ w_out,
        const float* __restrict__ b_out,
        const float* __restrict__ c1_w,
        const float* __restrict__ c1_b,
        const float* __restrict__ c2_w,
        const float* __restrict__ c2_b,
        const float* __restrict__ noise,
        float* __restrict__ out0,
        float* __restrict__ acts,
        float* __restrict__ pout) {
    extern __shared__ float sm[];
    unsigned* wh  = (unsigned*)(sm + SM_WHI);    // [64 kq][72] pairs
    unsigned* wl  = (unsigned*)(sm + SM_WLO);
    unsigned* hph = (unsigned*)(sm + SM_HPHI);   // [64 kq][136] pairs
    unsigned* hpl = (unsigned*)(sm + SM_HPLO);

    const int c    = blockIdx.x;
    const int tid  = threadIdx.x;
    const int lane = tid & 31;
    const int warp = tid >> 5;            // 0..7 : m-tile (b block 16*warp)
    // phase A roles
    const int kc = c >> 4, jc = c & 15;
    const int kc32 = kc * 32;
    const int la4 = lane & 3, ld4 = lane >> 2;
    const int bb = 16 * warp + ld4;
    // phase B roles
    const int b  = tid & 127;
    const int g  = tid >> 7;              // 0..1
    const int j0 = c * JPC;
    const int jg = j0 + 4 * g;            // 4 columns, jg multiple of 4

    // ---- P0a: classifier fusion ----
    {
        int idx = c * NTHR + tid;
        if (idx < NOUTn * Hn) g_comb[idx] = w_out[idx];
        if (idx < NCLSn * CLSOUTn * Hn) {
            int r = idx / Hn, h = idx % Hn;
            int j = r / CLSOUTn, o = r % CLSOUTn;
            float acc = 0.f;
            #pragma unroll
            for (int k = 0; k < BOTn; k++)
                acc += c2_w[(j * CLSOUTn + o) * BOTn + k] * c1_w[(j * BOTn + k) * Hn + h];
            g_comb[(NOUTn + r) * Hn + h] = acc;
        }
        if (idx < NOUTn) g_combb[idx] = b_out[idx];
        if (idx >= NOUTn && idx < NR) {
            int r = idx - NOUTn;
            int j = r / CLSOUTn, o = r % CLSOUTn;
            float acc = c2_b[j * CLSOUTn + o];
            #pragma unroll
            for (int k = 0; k < BOTn; k++)
                acc += c2_w[(j * CLSOUTn + o) * BOTn + k] * c1_b[j * BOTn + k];
            g_combb[idx] = acc;
        }
    }

    // ---- P0b: W slice as hi/lo bf16 k-pairs ----
    for (int idx = tid; idx < 64 * JSL; idx += NTHR) {
        int kq = idx >> 6, jl = idx & 63;
        int k0 = kc * KSL + 2 * kq, j = jc * JSL + jl;
        float w0 = fmaxf(w_rec[(size_t)k0 * Hn + j], 0.f);
        float w1 = fmaxf(w_rec[(size_t)(k0 + 1) * Hn + j], 0.f);
        if (k0 == j) w0 = 0.f;
        if (k0 + 1 == j) w1 = 0.f;
        w0 = (k0 < NEXC) ? w0 : -w0;
        w1 = (k0 + 1 < NEXC) ? w1 : -w1;
        float r0, r1;
        wh[kq * W_PITCH + jl] = pack_pair_hi(w0, w1, r0, r1);
        wl[kq * W_PITCH + jl] = pack_pair(r0, r1);
    }
    float br[4];
    #pragma unroll
    for (int jj = 0; jj < 4; jj++) br[jj] = b_rec[jg + jj];

    // ---- P0c: initial h_post(0) = 0, announce ----
    {
        int kq0 = jg >> 1;
        g_hph[0][kq0 * Bn + b] = 0u;
        g_hph[0][(kq0 + 1) * Bn + b] = 0u;
        g_hpl[0][kq0 * Bn + b] = 0u;
        g_hpl[0][(kq0 + 1) * Bn + b] = 0u;
    }
    announce(&g_hcnt[kc32]);

    // ---- P1: drive precompute ----
    {
        const int gg = tid >> 7;
        const int bbb = tid & 127;
        for (int u = c; u < Tn * 4; u += NCTA) {
            const int t = u % Tn;
            const int h0 = (u / Tn) * 256 + gg * 128;

            float sin_r[Sn], cin_r[Cn];
            const float4* sp = (const float4*)(stim + ((size_t)bbb * Tn + t) * Sn);
            #pragma unroll
            for (int p = 0; p < Sn / 4; p++) {
                float4 v = sp[p];
                sin_r[4*p] = v.x; sin_r[4*p+1] = v.y; sin_r[4*p+2] = v.z; sin_r[4*p+3] = v.w;
            }
            const float4* cpp = (const float4*)(ctx + ((size_t)bbb * Tn + t) * Cn);
            #pragma unroll
            for (int p = 0; p < Cn / 4; p++) {
                float4 v = cpp[p];
                cin_r[4*p] = v.x; cin_r[4*p+1] = v.y; cin_r[4*p+2] = v.z; cin_r[4*p+3] = v.w;
            }
            const float4* nzp = (const float4*)(noise + ((size_t)t * Bn + bbb) * Hn);

            for (int hh = 0; hh < 128; hh += 4) {
                const int h = h0 + hh;
                float acc0 = 0.f, acc1 = 0.f, acc2 = 0.f, acc3 = 0.f;
                #pragma unroll
                for (int s4 = 0; s4 < Sn / 4; s4++) {
                    float4 w0 = *(const float4*)(w_in + (size_t)(h + 0) * Sn + s4 * 4);
                    float4 w1 = *(const float4*)(w_in + (size_t)(h + 1) * Sn + s4 * 4);
                    float4 w2 = *(const float4*)(w_in + (size_t)(h + 2) * Sn + s4 * 4);
                    float4 w3 = *(const float4*)(w_in + (size_t)(h + 3) * Sn + s4 * 4);
                    float i0 = sin_r[4*s4], i1 = sin_r[4*s4+1];
                    float i2 = sin_r[4*s4+2], i3 = sin_r[4*s4+3];
                    acc0 = fmaf(i0, w0.x, acc0); acc0 = fmaf(i1, w0.y, acc0);
                    acc0 = fmaf(i2, w0.z, acc0); acc0 = fmaf(i3, w0.w, acc0);
                    acc1 = fmaf(i0, w1.x, acc1); acc1 = fmaf(i1, w1.y, acc1);
                    acc1 = fmaf(i2, w1.z, acc1); acc1 = fmaf(i3, w1.w, acc1);
                    acc2 = fmaf(i0, w2.x, acc2); acc2 = fmaf(i1, w2.y, acc2);
                    acc2 = fmaf(i2, w2.z, acc2); acc2 = fmaf(i3, w2.w, acc2);
                    acc3 = fmaf(i0, w3.x, acc3); acc3 = fmaf(i1, w3.y, acc3);
                    acc3 = fmaf(i2, w3.z, acc3); acc3 = fmaf(i3, w3.w, acc3);
                }
                #pragma unroll
                for (int c4 = 0; c4 < Cn / 4; c4++) {
                    float4 w0 = *(const float4*)(w_ctx + (size_t)(h + 0) * Cn + c4 * 4);
                    float4 w1 = *(const float4*)(w_ctx + (size_t)(h + 1) * Cn + c4 * 4);
                    float4 w2 = *(const float4*)(w_ctx + (size_t)(h + 2) * Cn + c4 * 4);
                    float4 w3 = *(const float4*)(w_ctx + (size_t)(h + 3) * Cn + c4 * 4);
                    float i0 = cin_r[4*c4], i1 = cin_r[4*c4+1];
                    float i2 = cin_r[4*c4+2], i3 = cin_r[4*c4+3];
                    acc0 = fmaf(i0, w0.x, acc0); acc0 = fmaf(i1, w0.y, acc0);
                    acc0 = fmaf(i2, w0.z, acc0); acc0 = fmaf(i3, w0.w, acc0);
                    acc1 = fmaf(i0, w1.x, acc1); acc1 = fmaf(i1, w1.y, acc1);
                    acc1 = fmaf(i2, w1.z, acc1); acc1 = fmaf(i3, w1.w, acc1);
                    acc2 = fmaf(i0, w2.x, acc2); acc2 = fmaf(i1, w2.y, acc2);
                    acc2 = fmaf(i2, w2.z, acc2); acc2 = fmaf(i3, w2.w, acc2);
                    acc3 = fmaf(i0, w3.x, acc3); acc3 = fmaf(i1, w3.y, acc3);
                    acc3 = fmaf(i2, w3.z, acc3); acc3 = fmaf(i3, w3.w, acc3);
                }
                float4 nz = nzp[h >> 2];
                float* gd = g_drive + ((size_t)t * Hn + h) * Bn + bbb;
                gd[0]      = fmaf(NZ_SCALE, nz.x, acc0);
                gd[Bn]     = fmaf(NZ_SCALE, nz.y, acc1);
                gd[2 * Bn] = fmaf(NZ_SCALE, nz.z, acc2);
                gd[3 * Bn] = fmaf(NZ_SCALE, nz.w, acc3);
            }
        }
    }

    gbar(NCTA);   // drive complete

    // ---- P2: scan ----
    float h[4], sx[4], su[4];
    #pragma unroll
    for (int jj = 0; jj < 4; jj++) {
        h[jj] = 0.f;
        sx[jj] = 1.f;
        su[jj] = (jj & 1) ? 0.15f : 0.45f;   // jg multiple of 4
    }

    const uint32_t hph_addr = (uint32_t)__cvta_generic_to_shared(hph);
    const uint32_t hpl_addr = (uint32_t)__cvta_generic_to_shared(hpl);

    for (int step = 0; step < Tn; step++) {
        const unsigned stp1 = 16u * (unsigned)(step + 1);
        const int par = step & 1;

        // drive prefetch (overlaps the flag wait)
        const float* gd = g_drive + ((size_t)step * Hn + jg) * Bn + b;
        float d0 = __ldcg(gd), d1 = __ldcg(gd + Bn);
        float d2 = __ldcg(gd + 2 * Bn), d3 = __ldcg(gd + 3 * Bn);

        // ---- wait: h_post pairs for my k-slice ready ----
        if (tid == 0) {
            while (ld_acq(&g_hcnt[kc32]) < stp1) { }
        }
        __syncthreads();

        // ---- phase A: stage hi/lo pair arrays, 2 pipelined stages ----
        {
            const unsigned* srch = g_hph[par] + (size_t)(kc * 64) * Bn;
            const unsigned* srcl = g_hpl[par] + (size_t)(kc * 64) * Bn;
            #pragma unroll
            for (int s = 0; s < 2; s++) {
                int rb = 32 * s;
                #pragma unroll
                for (int i = 0; i < 4; i++) {
                    int id = tid + i * 256;
                    int r = rb + (id >> 5), ch = id & 31;
                    cp_async16(hph_addr + r * (HP_PITCH * 4) + ch * 16,
                               (const char*)srch + r * 512 + ch * 16);
                }
                #pragma unroll
                for (int i = 0; i < 4; i++) {
                    int id = tid + i * 256;
                    int r = rb + (id >> 5), ch = id & 31;
                    cp_async16(hpl_addr + r * (HP_PITCH * 4) + ch * 16,
                               (const char*)srcl + r * 512 + ch * 16);
                }
                cp_commit();
            }
        }

        // ---- MMA GEMM: C[b 16-tile][j 8-tiles] over k=128 ----
        float C[8][4];
        #pragma unroll
        for (int nt = 0; nt < 8; nt++) {
            C[nt][0] = 0.f; C[nt][1] = 0.f; C[nt][2] = 0.f; C[nt][3] = 0.f;
        }

        #pragma unroll
        for (int t = 0; t < 8; t++) {
            if (t == 0) { cp_wait<1>(); __syncthreads(); }
            if (t == 4) { cp_wait<0>(); __syncthreads(); }
            const int kq = 8 * t + la4;
            unsigned ah0 = hph[kq * HP_PITCH + bb];
            unsigned ah1 = hph[kq * HP_PITCH + bb + 8];
            unsigned ah2 = hph[(kq + 4) * HP_PITCH + bb];
            unsigned ah3 = hph[(kq + 4) * HP_PITCH + bb + 8];
            unsigned al0 = hpl[kq * HP_PITCH + bb];
            unsigned al1 = hpl[kq * HP_PITCH + bb + 8];
            unsigned al2 = hpl[(kq + 4) * HP_PITCH + bb];
            unsigned al3 = hpl[(kq + 4) * HP_PITCH + bb + 8];
            #pragma unroll
            for (int nt = 0; nt < 8; nt++) {
                int jo = 8 * nt + ld4;
                unsigned bh0 = wh[kq * W_PITCH + jo];
                unsigned bh1 = wh[(kq + 4) * W_PITCH + jo];
                unsigned bl0 = wl[kq * W_PITCH + jo];
                unsigned bl1 = wl[(kq + 4) * W_PITCH + jo];
                MMA16816(C[nt], ah0, ah1, ah2, ah3, bh0, bh1);
                MMA16816(C[nt], ah0, ah1, ah2, ah3, bl0, bl1);
                MMA16816(C[nt], al0, al1, al2, al3, bh0, bh1);
            }
        }

        // write partials [kc][j][b]
        {
            float* gpart = g_part[par];
            #pragma unroll
            for (int nt = 0; nt < 8; nt++) {
                int j = jc * JSL + 8 * nt + 2 * la4;
                float* p0 = gpart + ((size_t)kc * Hn + j) * Bn;
                p0[bb]          = C[nt][0];
                p0[Bn + bb]     = C[nt][1];
                p0[bb + 8]      = C[nt][2];
                p0[Bn + bb + 8] = C[nt][3];
            }
        }

        announce(&g_kcnt[kc32]);

        // ---- phase B: wait all 8 partial groups ----
        if (tid == 0) {
            for (;;) {
                unsigned ok = 1;
                #pragma unroll
                for (int k2 = 0; k2 < NKC; k2++)
                    ok &= (ld_acq(&g_kcnt[k2 * 32]) >= stp1) ? 1u : 0u;
                if (ok) break;
            }
        }
        __syncthreads();

        float s0 = 0.f, s1 = 0.f, s2 = 0.f, s3 = 0.f;
        {
            const float* gpart = g_part[par];
            #pragma unroll
            for (int k2 = 0; k2 < NKC; k2++) {
                const float* pp = gpart + ((size_t)k2 * Hn + jg) * Bn + b;
                s0 += __ldcg(pp);
                s1 += __ldcg(pp + Bn);
                s2 += __ldcg(pp + 2 * Bn);
                s3 += __ldcg(pp + 3 * Bn);
            }
        }
        float ss[4] = {s0, s1, s2, s3};
        float dd[4] = {d0, d1, d2, d3};
        float hn[4], hp[4];
        #pragma unroll
        for (int jj = 0; jj < 4; jj++) {
            float val = h[jj] * (1.f - ALPHA_N)
                      + ALPHA_N * (dd[jj] + ss[jj] + br[jj]);
            hn[jj] = fmaxf(val, 0.f);
            h[jj] = hn[jj];
        }
        // STP + h_post(step+1) pairs, announce first, then acts store
        #pragma unroll
        for (int jj = 0; jj < 4; jj++) {
            const float axv = (jj & 1) ? AX_FAST : AX_SLOW;
            const float Uv  = (jj & 1) ? 0.15f : 0.45f;
            float hh = h[jj];
            float sxo = sx[jj], suo = su[jj];
            float sxn = sxo + axv * (1.f - sxo) - DT_SEC * suo * sxo * hh;
            float sun = suo + axv * (Uv - suo) + DT_SEC * Uv * (1.f - suo) * hh;
            sxn = fminf(fmaxf(sxn, 0.f), 1.f);
            sun = fminf(fmaxf(sun, 0.f), 1.f);
            sx[jj] = sxn; su[jj] = sun;
            hp[jj] = sun * sxn * hh;
        }
        {
            unsigned* dh = g_hph[par ^ 1];
            unsigned* dl = g_hpl[par ^ 1];
            int kq0 = jg >> 1;
            float r0, r1, r2, r3;
            unsigned h01 = pack_pair_hi(hp[0], hp[1], r0, r1);
            unsigned h23 = pack_pair_hi(hp[2], hp[3], r2, r3);
            dh[kq0 * Bn + b]       = h01;
            dh[(kq0 + 1) * Bn + b] = h23;
            dl[kq0 * Bn + b]       = pack_pair(r0, r1);
            dl[(kq0 + 1) * Bn + b] = pack_pair(r2, r3);
        }
        announce(&g_hcnt[kc32]);

        *(float4*)(acts + ((size_t)b * Tn + step) * Hn + jg) =
            make_float4(hn[0], hn[1], hn[2], hn[3]);
    }

    gbar(2 * NCTA);   // scan complete

    // ---- P3: post (fused readout) ----
    {
        float* s_comb = sm + SM_COMB;
        for (int i = tid; i < NR * Hn; i += NTHR) s_comb[i] = g_comb[i];
        __syncthreads();

        const float4* comb4 = (const float4*)s_comb;

        for (int u = c; u < (Bn * Tn) / PR_ROWS; u += NCTA) {
            #pragma unroll 1
            for (int rr = 0; rr < 4; rr++) {
                const int bt = u * PR_ROWS + warp * 4 + rr;
                const float4* a4 = (const float4*)(acts + (size_t)bt * Hn);

                float acc[NR];
                #pragma unroll
                for (int r = 0; r < NR; r++) acc[r] = 0.f;

                #pragma unroll
                for (int it = 0; it < Hn / 128; it++) {
                    float4 a = a4[it * 32 + lane];
                    #pragma unroll
                    for (int r = 0; r < NR; r++) {
                        float4 ww = comb4[r * 256 + it * 32 + lane];
                        float s = a.x * ww.x + a.y * ww.y;
                        s = fmaf(a.z, ww.z, s);
                        s = fmaf(a.w, ww.w, s);
                        acc[r] += s;
                    }
                }
                #pragma unroll
                for (int r = 0; r < NR; r++) {
                    #pragma unroll
                    for (int off = 16; off > 0; off >>= 1)
                        acc[r] += __shfl_down_sync(0xffffffffu, acc[r], off);
                }
                if (lane == 0) {
                    #pragma unroll
                    for (int r = 0; r < NOUTn; r++)
                        out0[(size_t)bt * NOUTn + r] = acc[r] + g_combb[r];
                    #pragma unroll
                    for (int r = NOUTn; r < NR; r++)
                        pout[(size_t)bt * (NCLSn * CLSOUTn) + (r - NOUTn)]
                            = acc[r] + g_combb[r];
                }
            }
        }
    }
}

// ---------------- launch ----------------
extern "C" void kernel_launch(void* const* d_in, const int* in_sizes, int n_in,
                              void* d_out, int out_size) {
    const float* stim  = (const float*)d_in[0];
    const float* ctx   = (const float*)d_in[1];
    const float* w_rec = (const float*)d_in[2];
    const float* b_rec = (const float*)d_in[3];
    const float* w_in  = (const float*)d_in[4];
    const float* w_ctx = (const float*)d_in[5];
    const float* w_out = (const float*)d_in[6];
    const float* b_out = (const float*)d_in[7];
    const float* c1_w  = (const float*)d_in[8];
    const float* c1_b  = (const float*)d_in[9];
    const float* c2_w  = (const float*)d_in[10];
    const float* c2_b  = (const float*)d_in[11];
    const float* noise = (const float*)d_in[12];

    float* out0 = (float*)d_out;                         // [B, T, 3]
    float* acts = out0 + (size_t)Bn * Tn * NOUTn;        // [B, T, H]
    float* pout = acts + (size_t)Bn * Tn * Hn;           // [B, T, 3, 8]

    static bool attr_set = false;
    if (!attr_set) {
        cudaFuncSetAttribute(mega_kernel,
                             cudaFuncAttributeMaxDynamicSharedMemorySize,
                             SMEM_BYTES);
        attr_set = true;
    }

    reset_kernel<<<1, 256>>>();
    mega_kernel<<<NCTA, NTHR, SMEM_BYTES>>>(
        stim, ctx, w_rec, b_rec, w_in, w_ctx, w_out, b_out,
        c1_w, c1_b, c2_w, c2_b, noise, out0, acts, pout);
}

// round 9
// speedup vs baseline: 1.7465x; 1.1996x over previous
#include <cuda_runtime.h>
#include <cuda_bf16.h>
#include <cstdint>

// Problem constants
#define Hn 1024
#define Bn 128
#define Tn 400
#define Sn 64
#define Cn 8
#define NOUTn 3
#define NCLSn 3
#define BOTn 2
#define CLSOUTn 8
#define NEXC 819              // int(1024 * 0.8)

#define NCTA 128
#define NTHR 256
#define JPC 8                 // j columns per CTA in phase B
#define KSL 128               // k-slice per CTA in phase A
#define JSL 64                // j-slice per CTA in phase A
#define NKC 8                 // number of k slices

#define ALPHA_N 0.2f
#define DT_SEC 0.02f
#define NZ_SCALE 0.25f        // NOISE_STD / ALPHA_N
#define AX_SLOW ((float)(20.0 / 1500.0))
#define AX_FAST ((float)(20.0 / 200.0))

#define NR (NOUTn + NCLSn * CLSOUTn)   // 27 fused readout rows
#define PR_ROWS 32

// smem word offsets
#define W_PITCH 72            // 64 j + 8 pad (words) -> conflict-free
#define HP_PITCH 136          // 128 b + 8 pad (words) -> conflict-free
#define SM_WHI 0              // 64 * 72 = 4608 words
#define SM_WLO 4608
#define SM_HPHI 9216          // 64 * 136 = 8704 words
#define SM_HPLO 17920
#define SM_COMB 0             // P3 reuses the W/hp space
#define SMEM_WORDS 27648      // max(26624 scan, 27648 comb)
#define SMEM_BYTES (SMEM_WORDS * 4)

// ---------------- device scratch ----------------
__device__ float g_drive[(size_t)Tn * Hn * Bn];        // [t][h][b], noise folded
__device__ unsigned g_hph[2][(Hn / 2) * Bn];           // h_post hi pairs [k/2][b]
__device__ unsigned g_hpl[2][(Hn / 2) * Bn];           // h_post lo pairs [k/2][b]
__device__ float g_part[2][(size_t)NKC * Hn * Bn];     // [par][kc][j][b]
__device__ float g_comb[NR * Hn];
__device__ float g_combb[NR];
__device__ unsigned g_count;                           // phase-transition counter
__device__ unsigned g_kcnt[NKC * 32];                  // partial-ready counts (padded)
__device__ unsigned g_hcnt[NKC * 32];                  // h_post-ready counts (padded)

// ---------------- sync helpers ----------------
// release edge: bar.sync (CTA cumulativity) + red.release.gpu. No separate
// MEMBAR needed: the release operation orders all prior stores observed by
// the releasing thread (which bar.sync guarantees includes the whole CTA).
__device__ __forceinline__ void red_rel(unsigned* p) {
    asm volatile("red.release.gpu.global.add.u32 [%0], 1;" :: "l"(p) : "memory");
}
// relaxed atomic load (morally strong, no ordering) for spin loops
__device__ __forceinline__ unsigned ld_rlx(const unsigned* p) {
    unsigned v;
    asm volatile("ld.relaxed.gpu.global.u32 %0, [%1];" : "=r"(v) : "l"(p) : "memory");
    return v;
}
// acquire upgrade after a relaxed spin passes
__device__ __forceinline__ void fence_acq() {
    asm volatile("fence.acq_rel.gpu;" ::: "memory");
}
__device__ __forceinline__ void announce(unsigned* p) {
    __syncthreads();
    if (threadIdx.x == 0) red_rel(p);
}

__device__ __forceinline__ void cp_async16(uint32_t saddr, const void* gaddr) {
    asm volatile("cp.async.cg.shared.global [%0], [%1], 16;" :: "r"(saddr), "l"(gaddr));
}
__device__ __forceinline__ void cp_commit() {
    asm volatile("cp.async.commit_group;");
}
template <int N>
__device__ __forceinline__ void cp_wait() {
    asm volatile("cp.async.wait_group %0;" :: "n"(N));
}

__device__ __forceinline__ void gbar(unsigned target) {
    __syncthreads();
    if (threadIdx.x == 0) {
        red_rel(&g_count);
        while (ld_rlx(&g_count) < target) { }
        fence_acq();
    }
    __syncthreads();
}

// bf16 split helpers
__device__ __forceinline__ unsigned pack_pair_hi(float e, float o,
                                                 float& re, float& ro) {
    __nv_bfloat16 he = __float2bfloat16(e);
    __nv_bfloat16 ho = __float2bfloat16(o);
    re = e - __bfloat162float(he);
    ro = o - __bfloat162float(ho);
    return ((unsigned)__bfloat16_as_ushort(ho) << 16) |
           (unsigned)__bfloat16_as_ushort(he);
}
__device__ __forceinline__ unsigned pack_pair(float e, float o) {
    __nv_bfloat16 he = __float2bfloat16(e);
    __nv_bfloat16 ho = __float2bfloat16(o);
    return ((unsigned)__bfloat16_as_ushort(ho) << 16) |
           (unsigned)__bfloat16_as_ushort(he);
}

#define MMA16816(cr, a0_, a1_, a2_, a3_, b0_, b1_)                          \
    asm volatile("mma.sync.aligned.m16n8k16.row.col.f32.bf16.bf16.f32 "     \
        "{%0,%1,%2,%3}, {%4,%5,%6,%7}, {%8,%9}, {%0,%1,%2,%3};"             \
        : "+f"((cr)[0]), "+f"((cr)[1]), "+f"((cr)[2]), "+f"((cr)[3])        \
        : "r"(a0_), "r"(a1_), "r"(a2_), "r"(a3_), "r"(b0_), "r"(b1_))

// ---------------- reset (graph-replay determinism) ----------------
__global__ void reset_kernel() {
    int i = threadIdx.x;
    if (i == 0) g_count = 0;
    if (i < NKC * 32) { g_kcnt[i] = 0; g_hcnt[i] = 0; }
}

// ---------------- the single persistent kernel ----------------
__global__ void __launch_bounds__(NTHR, 1) mega_kernel(
        const float* __restrict__ stim,
        const float* __restrict__ ctx,
        const float* __restrict__ w_rec,
        const float* __restrict__ b_rec,
        const float* __restrict__ w_in,
        const float* __restrict__ w_ctx,
        const float* __restrict__ w_out,
        const float* __restrict__ b_out,
        const float* __restrict__ c1_w,
        const float* __restrict__ c1_b,
        const float* __restrict__ c2_w,
        const float* __restrict__ c2_b,
        const float* __restrict__ noise,
        float* __restrict__ out0,
        float* __restrict__ acts,
        float* __restrict__ pout) {
    extern __shared__ float sm[];
    unsigned* wh  = (unsigned*)(sm + SM_WHI);    // [64 kq][72] pairs
    unsigned* wl  = (unsigned*)(sm + SM_WLO);
    unsigned* hph = (unsigned*)(sm + SM_HPHI);   // [64 kq][136] pairs
    unsigned* hpl = (unsigned*)(sm + SM_HPLO);

    const int c    = blockIdx.x;
    const int tid  = threadIdx.x;
    const int lane = tid & 31;
    const int warp = tid >> 5;            // 0..7 : m-tile (b block 16*warp)
    // phase A roles
    const int kc = c >> 4, jc = c & 15;
    const int kc32 = kc * 32;
    const int la4 = lane & 3, ld4 = lane >> 2;
    const int bb = 16 * warp + ld4;
    // phase B roles
    const int b  = tid & 127;
    const int g  = tid >> 7;              // 0..1
    const int j0 = c * JPC;
    const int jg = j0 + 4 * g;            // 4 columns, jg multiple of 4

    // ---- P0a: classifier fusion ----
    {
        int idx = c * NTHR + tid;
        if (idx < NOUTn * Hn) g_comb[idx] = w_out[idx];
        if (idx < NCLSn * CLSOUTn * Hn) {
            int r = idx / Hn, h = idx % Hn;
            int j = r / CLSOUTn, o = r % CLSOUTn;
            float acc = 0.f;
            #pragma unroll
            for (int k = 0; k < BOTn; k++)
                acc += c2_w[(j * CLSOUTn + o) * BOTn + k] * c1_w[(j * BOTn + k) * Hn + h];
            g_comb[(NOUTn + r) * Hn + h] = acc;
        }
        if (idx < NOUTn) g_combb[idx] = b_out[idx];
        if (idx >= NOUTn && idx < NR) {
            int r = idx - NOUTn;
            int j = r / CLSOUTn, o = r % CLSOUTn;
            float acc = c2_b[j * CLSOUTn + o];
            #pragma unroll
            for (int k = 0; k < BOTn; k++)
                acc += c2_w[(j * CLSOUTn + o) * BOTn + k] * c1_b[j * BOTn + k];
            g_combb[idx] = acc;
        }
    }

    // ---- P0b: W slice as hi/lo bf16 k-pairs ----
    for (int idx = tid; idx < 64 * JSL; idx += NTHR) {
        int kq = idx >> 6, jl = idx & 63;
        int k0 = kc * KSL + 2 * kq, j = jc * JSL + jl;
        float w0 = fmaxf(w_rec[(size_t)k0 * Hn + j], 0.f);
        float w1 = fmaxf(w_rec[(size_t)(k0 + 1) * Hn + j], 0.f);
        if (k0 == j) w0 = 0.f;
        if (k0 + 1 == j) w1 = 0.f;
        w0 = (k0 < NEXC) ? w0 : -w0;
        w1 = (k0 + 1 < NEXC) ? w1 : -w1;
        float r0, r1;
        wh[kq * W_PITCH + jl] = pack_pair_hi(w0, w1, r0, r1);
        wl[kq * W_PITCH + jl] = pack_pair(r0, r1);
    }
    float br[4];
    #pragma unroll
    for (int jj = 0; jj < 4; jj++) br[jj] = b_rec[jg + jj];

    // ---- P0c: initial h_post(0) = 0, announce ----
    {
        int kq0 = jg >> 1;
        g_hph[0][kq0 * Bn + b] = 0u;
        g_hph[0][(kq0 + 1) * Bn + b] = 0u;
        g_hpl[0][kq0 * Bn + b] = 0u;
        g_hpl[0][(kq0 + 1) * Bn + b] = 0u;
    }
    announce(&g_hcnt[kc32]);

    // ---- P1: drive precompute ----
    {
        const int gg = tid >> 7;
        const int bbb = tid & 127;
        for (int u = c; u < Tn * 4; u += NCTA) {
            const int t = u % Tn;
            const int h0 = (u / Tn) * 256 + gg * 128;

            float sin_r[Sn], cin_r[Cn];
            const float4* sp = (const float4*)(stim + ((size_t)bbb * Tn + t) * Sn);
            #pragma unroll
            for (int p = 0; p < Sn / 4; p++) {
                float4 v = sp[p];
                sin_r[4*p] = v.x; sin_r[4*p+1] = v.y; sin_r[4*p+2] = v.z; sin_r[4*p+3] = v.w;
            }
            const float4* cpp = (const float4*)(ctx + ((size_t)bbb * Tn + t) * Cn);
            #pragma unroll
            for (int p = 0; p < Cn / 4; p++) {
                float4 v = cpp[p];
                cin_r[4*p] = v.x; cin_r[4*p+1] = v.y; cin_r[4*p+2] = v.z; cin_r[4*p+3] = v.w;
            }
            const float4* nzp = (const float4*)(noise + ((size_t)t * Bn + bbb) * Hn);

            for (int hh = 0; hh < 128; hh += 4) {
                const int h = h0 + hh;
                float acc0 = 0.f, acc1 = 0.f, acc2 = 0.f, acc3 = 0.f;
                #pragma unroll
                for (int s4 = 0; s4 < Sn / 4; s4++) {
                    float4 w0 = *(const float4*)(w_in + (size_t)(h + 0) * Sn + s4 * 4);
                    float4 w1 = *(const float4*)(w_in + (size_t)(h + 1) * Sn + s4 * 4);
                    float4 w2 = *(const float4*)(w_in + (size_t)(h + 2) * Sn + s4 * 4);
                    float4 w3 = *(const float4*)(w_in + (size_t)(h + 3) * Sn + s4 * 4);
                    float i0 = sin_r[4*s4], i1 = sin_r[4*s4+1];
                    float i2 = sin_r[4*s4+2], i3 = sin_r[4*s4+3];
                    acc0 = fmaf(i0, w0.x, acc0); acc0 = fmaf(i1, w0.y, acc0);
                    acc0 = fmaf(i2, w0.z, acc0); acc0 = fmaf(i3, w0.w, acc0);
                    acc1 = fmaf(i0, w1.x, acc1); acc1 = fmaf(i1, w1.y, acc1);
                    acc1 = fmaf(i2, w1.z, acc1); acc1 = fmaf(i3, w1.w, acc1);
                    acc2 = fmaf(i0, w2.x, acc2); acc2 = fmaf(i1, w2.y, acc2);
                    acc2 = fmaf(i2, w2.z, acc2); acc2 = fmaf(i3, w2.w, acc2);
                    acc3 = fmaf(i0, w3.x, acc3); acc3 = fmaf(i1, w3.y, acc3);
                    acc3 = fmaf(i2, w3.z, acc3); acc3 = fmaf(i3, w3.w, acc3);
                }
                #pragma unroll
                for (int c4 = 0; c4 < Cn / 4; c4++) {
                    float4 w0 = *(const float4*)(w_ctx + (size_t)(h + 0) * Cn + c4 * 4);
                    float4 w1 = *(const float4*)(w_ctx + (size_t)(h + 1) * Cn + c4 * 4);
                    float4 w2 = *(const float4*)(w_ctx + (size_t)(h + 2) * Cn + c4 * 4);
                    float4 w3 = *(const float4*)(w_ctx + (size_t)(h + 3) * Cn + c4 * 4);
                    float i0 = cin_r[4*c4], i1 = cin_r[4*c4+1];
                    float i2 = cin_r[4*c4+2], i3 = cin_r[4*c4+3];
                    acc0 = fmaf(i0, w0.x, acc0); acc0 = fmaf(i1, w0.y, acc0);
                    acc0 = fmaf(i2, w0.z, acc0); acc0 = fmaf(i3, w0.w, acc0);
                    acc1 = fmaf(i0, w1.x, acc1); acc1 = fmaf(i1, w1.y, acc1);
                    acc1 = fmaf(i2, w1.z, acc1); acc1 = fmaf(i3, w1.w, acc1);
                    acc2 = fmaf(i0, w2.x, acc2); acc2 = fmaf(i1, w2.y, acc2);
                    acc2 = fmaf(i2, w2.z, acc2); acc2 = fmaf(i3, w2.w, acc2);
                    acc3 = fmaf(i0, w3.x, acc3); acc3 = fmaf(i1, w3.y, acc3);
                    acc3 = fmaf(i2, w3.z, acc3); acc3 = fmaf(i3, w3.w, acc3);
                }
                float4 nz = nzp[h >> 2];
                float* gd = g_drive + ((size_t)t * Hn + h) * Bn + bbb;
                gd[0]      = fmaf(NZ_SCALE, nz.x, acc0);
                gd[Bn]     = fmaf(NZ_SCALE, nz.y, acc1);
                gd[2 * Bn] = fmaf(NZ_SCALE, nz.z, acc2);
                gd[3 * Bn] = fmaf(NZ_SCALE, nz.w, acc3);
            }
        }
    }

    gbar(NCTA);   // drive complete

    // ---- P2: scan ----
    float h[4], sx[4], su[4];
    #pragma unroll
    for (int jj = 0; jj < 4; jj++) {
        h[jj] = 0.f;
        sx[jj] = 1.f;
        su[jj] = (jj & 1) ? 0.15f : 0.45f;   // jg multiple of 4
    }

    const uint32_t hph_addr = (uint32_t)__cvta_generic_to_shared(hph);
    const uint32_t hpl_addr = (uint32_t)__cvta_generic_to_shared(hpl);

    for (int step = 0; step < Tn; step++) {
        const unsigned stp1 = 16u * (unsigned)(step + 1);
        const int par = step & 1;

        // drive prefetch (overlaps the flag wait)
        const float* gd = g_drive + ((size_t)step * Hn + jg) * Bn + b;
        float d0 = __ldcg(gd), d1 = __ldcg(gd + Bn);
        float d2 = __ldcg(gd + 2 * Bn), d3 = __ldcg(gd + 3 * Bn);

        // ---- wait: h_post pairs for my k-slice ready (relaxed spin + fence) ----
        if (tid == 0) {
            while (ld_rlx(&g_hcnt[kc32]) < stp1) { }
            fence_acq();
        }
        __syncthreads();

        // ---- phase A: stage hi/lo pair arrays, 2 pipelined stages ----
        {
            const unsigned* srch = g_hph[par] + (size_t)(kc * 64) * Bn;
            const unsigned* srcl = g_hpl[par] + (size_t)(kc * 64) * Bn;
            #pragma unroll
            for (int s = 0; s < 2; s++) {
                int rb = 32 * s;
                #pragma unroll
                for (int i = 0; i < 4; i++) {
                    int id = tid + i * 256;
                    int r = rb + (id >> 5), ch = id & 31;
                    cp_async16(hph_addr + r * (HP_PITCH * 4) + ch * 16,
                               (const char*)srch + r * 512 + ch * 16);
                }
                #pragma unroll
                for (int i = 0; i < 4; i++) {
                    int id = tid + i * 256;
                    int r = rb + (id >> 5), ch = id & 31;
                    cp_async16(hpl_addr + r * (HP_PITCH * 4) + ch * 16,
                               (const char*)srcl + r * 512 + ch * 16);
                }
                cp_commit();
            }
        }

        // ---- MMA GEMM: C[b 16-tile][j 8-tiles] over k=128 ----
        float C[8][4];
        #pragma unroll
        for (int nt = 0; nt < 8; nt++) {
            C[nt][0] = 0.f; C[nt][1] = 0.f; C[nt][2] = 0.f; C[nt][3] = 0.f;
        }

        #pragma unroll
        for (int t = 0; t < 8; t++) {
            if (t == 0) { cp_wait<1>(); __syncthreads(); }
            if (t == 4) { cp_wait<0>(); __syncthreads(); }
            const int kq = 8 * t + la4;
            unsigned ah0 = hph[kq * HP_PITCH + bb];
            unsigned ah1 = hph[kq * HP_PITCH + bb + 8];
            unsigned ah2 = hph[(kq + 4) * HP_PITCH + bb];
            unsigned ah3 = hph[(kq + 4) * HP_PITCH + bb + 8];
            unsigned al0 = hpl[kq * HP_PITCH + bb];
            unsigned al1 = hpl[kq * HP_PITCH + bb + 8];
            unsigned al2 = hpl[(kq + 4) * HP_PITCH + bb];
            unsigned al3 = hpl[(kq + 4) * HP_PITCH + bb + 8];
            #pragma unroll
            for (int nt = 0; nt < 8; nt++) {
                int jo = 8 * nt + ld4;
                unsigned bh0 = wh[kq * W_PITCH + jo];
                unsigned bh1 = wh[(kq + 4) * W_PITCH + jo];
                unsigned bl0 = wl[kq * W_PITCH + jo];
                unsigned bl1 = wl[(kq + 4) * W_PITCH + jo];
                MMA16816(C[nt], ah0, ah1, ah2, ah3, bh0, bh1);
                MMA16816(C[nt], ah0, ah1, ah2, ah3, bl0, bl1);
                MMA16816(C[nt], al0, al1, al2, al3, bh0, bh1);
            }
        }

        // write partials [kc][j][b]
        {
            float* gpart = g_part[par];
            #pragma unroll
            for (int nt = 0; nt < 8; nt++) {
                int j = jc * JSL + 8 * nt + 2 * la4;
                float* p0 = gpart + ((size_t)kc * Hn + j) * Bn;
                p0[bb]          = C[nt][0];
                p0[Bn + bb]     = C[nt][1];
                p0[bb + 8]      = C[nt][2];
                p0[Bn + bb + 8] = C[nt][3];
            }
        }

        announce(&g_kcnt[kc32]);

        // ---- phase B: wait all 8 partial groups (relaxed spins, MLP=8) ----
        if (tid == 0) {
            for (;;) {
                unsigned ok = 1;
                #pragma unroll
                for (int k2 = 0; k2 < NKC; k2++)
                    ok &= (ld_rlx(&g_kcnt[k2 * 32]) >= stp1) ? 1u : 0u;
                if (ok) break;
            }
            fence_acq();
        }
        __syncthreads();

        float s0 = 0.f, s1 = 0.f, s2 = 0.f, s3 = 0.f;
        {
            const float* gpart = g_part[par];
            #pragma unroll
            for (int k2 = 0; k2 < NKC; k2++) {
                const float* pp = gpart + ((size_t)k2 * Hn + jg) * Bn + b;
                s0 += __ldcg(pp);
                s1 += __ldcg(pp + Bn);
                s2 += __ldcg(pp + 2 * Bn);
                s3 += __ldcg(pp + 3 * Bn);
            }
        }
        float ss[4] = {s0, s1, s2, s3};
        float dd[4] = {d0, d1, d2, d3};
        float hn[4], hp[4];
        #pragma unroll
        for (int jj = 0; jj < 4; jj++) {
            float val = h[jj] * (1.f - ALPHA_N)
                      + ALPHA_N * (dd[jj] + ss[jj] + br[jj]);
            hn[jj] = fmaxf(val, 0.f);
            h[jj] = hn[jj];
        }
        // STP + h_post(step+1) pairs, announce first, then acts store
        #pragma unroll
        for (int jj = 0; jj < 4; jj++) {
            const float axv = (jj & 1) ? AX_FAST : AX_SLOW;
            const float Uv  = (jj & 1) ? 0.15f : 0.45f;
            float hh = h[jj];
            float sxo = sx[jj], suo = su[jj];
            float sxn = sxo + axv * (1.f - sxo) - DT_SEC * suo * sxo * hh;
            float sun = suo + axv * (Uv - suo) + DT_SEC * Uv * (1.f - suo) * hh;
            sxn = fminf(fmaxf(sxn, 0.f), 1.f);
            sun = fminf(fmaxf(sun, 0.f), 1.f);
            sx[jj] = sxn; su[jj] = sun;
            hp[jj] = sun * sxn * hh;
        }
        {
            unsigned* dh = g_hph[par ^ 1];
            unsigned* dl = g_hpl[par ^ 1];
            int kq0 = jg >> 1;
            float r0, r1, r2, r3;
            unsigned h01 = pack_pair_hi(hp[0], hp[1], r0, r1);
            unsigned h23 = pack_pair_hi(hp[2], hp[3], r2, r3);
            dh[kq0 * Bn + b]       = h01;
            dh[(kq0 + 1) * Bn + b] = h23;
            dl[kq0 * Bn + b]       = pack_pair(r0, r1);
            dl[(kq0 + 1) * Bn + b] = pack_pair(r2, r3);
        }
        announce(&g_hcnt[kc32]);

        *(float4*)(acts + ((size_t)b * Tn + step) * Hn + jg) =
            make_float4(hn[0], hn[1], hn[2], hn[3]);
    }

    gbar(2 * NCTA);   // scan complete

    // ---- P3: post (fused readout) ----
    {
        float* s_comb = sm + SM_COMB;
        for (int i = tid; i < NR * Hn; i += NTHR) s_comb[i] = g_comb[i];
        __syncthreads();

        const float4* comb4 = (const float4*)s_comb;

        for (int u = c; u < (Bn * Tn) / PR_ROWS; u += NCTA) {
            #pragma unroll 1
            for (int rr = 0; rr < 4; rr++) {
                const int bt = u * PR_ROWS + warp * 4 + rr;
                const float4* a4 = (const float4*)(acts + (size_t)bt * Hn);

                float acc[NR];
                #pragma unroll
                for (int r = 0; r < NR; r++) acc[r] = 0.f;

                #pragma unroll
                for (int it = 0; it < Hn / 128; it++) {
                    float4 a = a4[it * 32 + lane];
                    #pragma unroll
                    for (int r = 0; r < NR; r++) {
                        float4 ww = comb4[r * 256 + it * 32 + lane];
                        float s = a.x * ww.x + a.y * ww.y;
                        s = fmaf(a.z, ww.z, s);
                        s = fmaf(a.w, ww.w, s);
                        acc[r] += s;
                    }
                }
                #pragma unroll
                for (int r = 0; r < NR; r++) {
                    #pragma unroll
                    for (int off = 16; off > 0; off >>= 1)
                        acc[r] += __shfl_down_sync(0xffffffffu, acc[r], off);
                }
                if (lane == 0) {
                    #pragma unroll
                    for (int r = 0; r < NOUTn; r++)
                        out0[(size_t)bt * NOUTn + r] = acc[r] + g_combb[r];
                    #pragma unroll
                    for (int r = NOUTn; r < NR; r++)
                        pout[(size_t)bt * (NCLSn * CLSOUTn) + (r - NOUTn)]
                            = acc[r] + g_combb[r];
                }
            }
        }
    }
}

// ---------------- launch ----------------
extern "C" void kernel_launch(void* const* d_in, const int* in_sizes, int n_in,
                              void* d_out, int out_size) {
    const float* stim  = (const float*)d_in[0];
    const float* ctx   = (const float*)d_in[1];
    const float* w_rec = (const float*)d_in[2];
    const float* b_rec = (const float*)d_in[3];
    const float* w_in  = (const float*)d_in[4];
    const float* w_ctx = (const float*)d_in[5];
    const float* w_out = (const float*)d_in[6];
    const float* b_out = (const float*)d_in[7];
    const float* c1_w  = (const float*)d_in[8];
    const float* c1_b  = (const float*)d_in[9];
    const float* c2_w  = (const float*)d_in[10];
    const float* c2_b  = (const float*)d_in[11];
    const float* noise = (const float*)d_in[12];

    float* out0 = (float*)d_out;                         // [B, T, 3]
    float* acts = out0 + (size_t)Bn * Tn * NOUTn;        // [B, T, H]
    float* pout = acts + (size_t)Bn * Tn * Hn;           // [B, T, 3, 8]

    static bool attr_set = false;
    if (!attr_set) {
        cudaFuncSetAttribute(mega_kernel,
                             cudaFuncAttributeMaxDynamicSharedMemorySize,
                             SMEM_BYTES);
        attr_set = true;
    }

    reset_kernel<<<1, 256>>>();
    mega_kernel<<<NCTA, NTHR, SMEM_BYTES>>>(
        stim, ctx, w_rec, b_rec, w_in, w_ctx, w_out, b_out,
        c1_w, c1_b, c2_w, c2_b, noise, out0, acts, pout);
}